// round 1
// baseline (speedup 1.0000x reference)
#include <cuda_runtime.h>
#include <math.h>

#define Bc 8
#define Dm 384
#define Hh 6
#define HD 64
#define Lc 12
#define MLPD 1536
#define NCLSD 1000
#define TMAX 577
#define NPATCH 576
#define GG 24

// ---------------- scratch (device globals; no allocation allowed) ----------------
__device__ float g_patches[Bc * NPATCH * 768];
__device__ float g_xA[Bc * TMAX * Dm];
__device__ float g_xB[Bc * TMAX * Dm];
__device__ float g_xn[Bc * TMAX * Dm];
__device__ float g_qkv[Bc * TMAX * 3 * Dm];
__device__ float g_S[(size_t)Bc * Hh * TMAX * TMAX];   // 63.9 MB attention matrix
__device__ float g_ao[Bc * TMAX * Dm];
__device__ float g_hid[Bc * TMAX * MLPD];
__device__ float g_rho_bh[Bc * Hh];
__device__ float g_raw[Bc * NPATCH];
__device__ float g_mass[Bc];
__device__ float g_prevmass[Bc];
__device__ float g_scores[NPATCH];
__device__ int   g_keep[TMAX];
__device__ int   g_Ntok;     // current token count (patches + cls)
__device__ int   g_Nnext;    // next patch count
__device__ int   g_hasprev;

// ---------------- init ----------------
__global__ void k_init() { g_Ntok = TMAX; g_hasprev = 0; }

// ---------------- patchify: x[B,3,384,384] -> patches[B,576,768] ----------------
__global__ void k_patchify(const float* __restrict__ x) {
    int p = blockIdx.x, b = blockIdx.y;
    int gy = p / GG, gx = p % GG;
    for (int f = threadIdx.x; f < 768; f += blockDim.x) {
        int c = f >> 8, r = (f >> 4) & 15, cc = f & 15;
        g_patches[((size_t)(b * NPATCH + p)) * 768 + f] =
            x[(((size_t)(b * 3 + c)) * 384 + gy * 16 + r) * 384 + gx * 16 + cc];
    }
}

// ---------------- generic fp32 GEMM: C[b,t,:] = act(A[b,t,:]@W + bias) (+res) ---
// A: [B][rows][K], W: [K][N], C/res: [B][rows][N]
__global__ void __launch_bounds__(256) k_gemm(
    const float* __restrict__ A, int rows, int K,
    const float* __restrict__ W, int N,
    const float* __restrict__ bias,
    const float* __restrict__ res,
    float* __restrict__ C,
    int act, int useDyn, int ntokFixed)
{
    int ntok = useDyn ? g_Ntok : ntokFixed;
    int b  = blockIdx.z;
    int t0 = blockIdx.y * 64;
    int n0 = blockIdx.x * 64;
    if (t0 >= ntok) return;

    __shared__ float As[16][64];
    __shared__ float Bs[16][68];
    int tid = threadIdx.x;
    int tx = tid & 15, ty = tid >> 4;
    float acc[4][4] = {};
    const float* Ab = A + (size_t)b * rows * K;

    for (int k0 = 0; k0 < K; k0 += 16) {
        #pragma unroll
        for (int i = 0; i < 4; i++) {
            int e = tid + i * 256;
            int r = e >> 4, kk = e & 15;
            int t = t0 + r;
            As[kk][r] = (t < rows) ? Ab[(size_t)t * K + k0 + kk] : 0.f;
        }
        #pragma unroll
        for (int i = 0; i < 4; i++) {
            int e = tid + i * 256;
            int kk = e >> 6, n = e & 63;
            Bs[kk][n] = W[(size_t)(k0 + kk) * N + n0 + n];
        }
        __syncthreads();
        #pragma unroll
        for (int kk = 0; kk < 16; kk++) {
            float a0 = As[kk][ty * 4 + 0], a1 = As[kk][ty * 4 + 1];
            float a2 = As[kk][ty * 4 + 2], a3 = As[kk][ty * 4 + 3];
            float b0 = Bs[kk][tx * 4 + 0], b1 = Bs[kk][tx * 4 + 1];
            float b2 = Bs[kk][tx * 4 + 2], b3 = Bs[kk][tx * 4 + 3];
            acc[0][0] += a0 * b0; acc[0][1] += a0 * b1; acc[0][2] += a0 * b2; acc[0][3] += a0 * b3;
            acc[1][0] += a1 * b0; acc[1][1] += a1 * b1; acc[1][2] += a1 * b2; acc[1][3] += a1 * b3;
            acc[2][0] += a2 * b0; acc[2][1] += a2 * b1; acc[2][2] += a2 * b2; acc[2][3] += a2 * b3;
            acc[3][0] += a3 * b0; acc[3][1] += a3 * b1; acc[3][2] += a3 * b2; acc[3][3] += a3 * b3;
        }
        __syncthreads();
    }
    #pragma unroll
    for (int i = 0; i < 4; i++) {
        int t = t0 + ty * 4 + i;
        if (t >= rows) continue;
        float* Crow = C + ((size_t)b * rows + t) * N;
        const float* Rrow = res ? res + ((size_t)b * rows + t) * N : (const float*)0;
        #pragma unroll
        for (int j = 0; j < 4; j++) {
            int n = n0 + tx * 4 + j;
            float v = acc[i][j] + bias[n];
            if (act == 1) v = 0.5f * v * (1.f + erff(v * 0.70710678118654752f));
            if (Rrow) v += Rrow[n];
            Crow[n] = v;
        }
    }
}

// ---------------- embed: xcur = [cls | tok] + pos ----------------
__global__ void k_embed(const float* __restrict__ cls, const float* __restrict__ pos,
                        const float* __restrict__ tok, float* __restrict__ X) {
    int t = blockIdx.x, b = blockIdx.y, d = threadIdx.x;
    float v = (t == 0) ? cls[d] : tok[((size_t)(b * NPATCH + t - 1)) * Dm + d];
    X[((size_t)(b * TMAX + t)) * Dm + d] = v + pos[(size_t)t * Dm + d];
}

// ---------------- LayerNorm ----------------
__global__ void k_ln(const float* __restrict__ X, const float* __restrict__ s,
                     const float* __restrict__ bb, float* __restrict__ O,
                     int useDyn, int ntokFixed) {
    int ntok = useDyn ? g_Ntok : ntokFixed;
    int t = blockIdx.x; if (t >= ntok) return;
    int b = blockIdx.y;
    const float* xr = X + ((size_t)(b * TMAX + t)) * Dm;
    __shared__ float red[128];
    int tid = threadIdx.x;
    float v0 = xr[tid], v1 = xr[tid + 128], v2 = xr[tid + 256];
    red[tid] = v0 + v1 + v2; __syncthreads();
    for (int st = 64; st > 0; st >>= 1) { if (tid < st) red[tid] += red[tid + st]; __syncthreads(); }
    float mean = red[0] / 384.f; __syncthreads();
    float d0 = v0 - mean, d1 = v1 - mean, d2 = v2 - mean;
    red[tid] = d0 * d0 + d1 * d1 + d2 * d2; __syncthreads();
    for (int st = 64; st > 0; st >>= 1) { if (tid < st) red[tid] += red[tid + st]; __syncthreads(); }
    float var = red[0] / 384.f;
    float inv = 1.f / sqrtf(var + 1e-5f);
    float* orow = O + ((size_t)(b * TMAX + t)) * Dm;
    orow[tid]       = d0 * inv * s[tid]       + bb[tid];
    orow[tid + 128] = d1 * inv * s[tid + 128] + bb[tid + 128];
    orow[tid + 256] = d2 * inv * s[tid + 256] + bb[tid + 256];
}

// ---------------- attention scores S = Q K^T * hd^-0.5 ----------------
__global__ void __launch_bounds__(256) k_qk(const float* __restrict__ qkv) {
    int ntok = g_Ntok;
    int b = blockIdx.z / Hh, h = blockIdx.z % Hh;
    int q0 = blockIdx.y * 32, k0 = blockIdx.x * 32;
    if (q0 >= ntok || k0 >= ntok) return;
    __shared__ float Qs[32][64];
    __shared__ float Ks[32][65];
    int tid = threadIdx.x;
    for (int i = tid; i < 2048; i += 256) {
        int r = i >> 6, d = i & 63;
        int tq = q0 + r, tk = k0 + r;
        Qs[r][d] = (tq < ntok) ? qkv[((size_t)(b * TMAX + tq)) * 1152 + h * 64 + d] : 0.f;
        Ks[r][d] = (tk < ntok) ? qkv[((size_t)(b * TMAX + tk)) * 1152 + 384 + h * 64 + d] : 0.f;
    }
    __syncthreads();
    int tx = tid & 31, ty = tid >> 5;
    float acc[4] = {0.f, 0.f, 0.f, 0.f};
    #pragma unroll 8
    for (int d = 0; d < 64; d++) {
        float kv = Ks[tx][d];
        acc[0] += Qs[ty][d] * kv;
        acc[1] += Qs[ty + 8][d] * kv;
        acc[2] += Qs[ty + 16][d] * kv;
        acc[3] += Qs[ty + 24][d] * kv;
    }
    int kcol = k0 + tx;
    if (kcol < ntok) {
        float* Sb = g_S + ((size_t)(b * Hh + h)) * TMAX * TMAX;
        #pragma unroll
        for (int i = 0; i < 4; i++) {
            int q = q0 + ty + 8 * i;
            if (q < ntok) Sb[(size_t)q * TMAX + kcol] = acc[i] * 0.125f;
        }
    }
}

// ---------------- softmax rows (in place) ----------------
__global__ void k_softmax() {
    int ntok = g_Ntok;
    int q = blockIdx.x; if (q >= ntok) return;
    int bh = blockIdx.y;
    float* row = g_S + ((size_t)bh * TMAX + q) * TMAX;
    __shared__ float red[256];
    int tid = threadIdx.x;
    float v[3]; float mx = -1e30f;
    #pragma unroll
    for (int i = 0; i < 3; i++) {
        int k = tid + 256 * i;
        v[i] = (k < ntok) ? row[k] : -1e30f;
        mx = fmaxf(mx, v[i]);
    }
    red[tid] = mx; __syncthreads();
    for (int st = 128; st > 0; st >>= 1) { if (tid < st) red[tid] = fmaxf(red[tid], red[tid + st]); __syncthreads(); }
    mx = red[0]; __syncthreads();
    float sm = 0.f;
    #pragma unroll
    for (int i = 0; i < 3; i++) {
        int k = tid + 256 * i;
        v[i] = (k < ntok) ? expf(v[i] - mx) : 0.f;
        sm += v[i];
    }
    red[tid] = sm; __syncthreads();
    for (int st = 128; st > 0; st >>= 1) { if (tid < st) red[tid] += red[tid + st]; __syncthreads(); }
    float inv = 1.f / red[0];
    #pragma unroll
    for (int i = 0; i < 3; i++) {
        int k = tid + 256 * i;
        if (k < ntok) row[k] = v[i] * inv;
    }
}

// ---------------- out = attn @ V ----------------
__global__ void __launch_bounds__(256) k_av(const float* __restrict__ qkv) {
    int ntok = g_Ntok;
    int q0 = blockIdx.x * 32; if (q0 >= ntok) return;
    int h = blockIdx.y, b = blockIdx.z;
    __shared__ float Ps[32][33];
    __shared__ float Vs[32][65];
    int tid = threadIdx.x;
    int tx = tid & 63, ty = tid >> 6;
    float acc[8] = {};
    const float* Sb = g_S + ((size_t)(b * Hh + h)) * TMAX * TMAX;
    for (int k0 = 0; k0 < ntok; k0 += 32) {
        for (int i = tid; i < 1024; i += 256) {
            int r = i >> 5, c = i & 31;
            int q = q0 + r, k = k0 + c;
            Ps[r][c] = (q < ntok && k < ntok) ? Sb[(size_t)q * TMAX + k] : 0.f;
        }
        for (int i = tid; i < 2048; i += 256) {
            int r = i >> 6, d = i & 63;
            int k = k0 + r;
            Vs[r][d] = (k < ntok) ? qkv[((size_t)(b * TMAX + k)) * 1152 + 768 + h * 64 + d] : 0.f;
        }
        __syncthreads();
        #pragma unroll
        for (int kk = 0; kk < 32; kk++) {
            float vv = Vs[kk][tx];
            #pragma unroll
            for (int i = 0; i < 8; i++) acc[i] += Ps[ty + 4 * i][kk] * vv;
        }
        __syncthreads();
    }
    #pragma unroll
    for (int i = 0; i < 8; i++) {
        int q = q0 + ty + 4 * i;
        if (q < ntok) g_ao[((size_t)(b * TMAX + q)) * Dm + h * 64 + tx] = acc[i];
    }
}

// ---------------- CLS entropy per (b,h) ----------------
__global__ void k_ent() {
    int ntok = g_Ntok;
    int bh = blockIdx.x;
    const float* row = g_S + ((size_t)bh) * TMAX * TMAX;   // q = 0
    __shared__ float red[256];
    int tid = threadIdx.x;
    float s = 0.f;
    for (int k = tid; k < ntok; k += 256) { float p = row[k]; s += p * logf(p + 1e-6f); }
    red[tid] = s; __syncthreads();
    for (int st = 128; st > 0; st >>= 1) { if (tid < st) red[tid] += red[tid + st]; __syncthreads(); }
    if (tid == 0) g_rho_bh[bh] = -red[0] / logf((float)ntok);
}

// ---------------- raw[b,k] = sum_h attn[b,h,0,k+1] * ||v[b,h,k+1]|| ----------------
__global__ void k_raw(const float* __restrict__ qkv) {
    int ntok = g_Ntok;
    int k = blockIdx.x, b = blockIdx.y;
    if (k + 1 >= ntok) return;
    __shared__ float red[64];
    __shared__ float racc;
    int tid = threadIdx.x;
    if (tid == 0) racc = 0.f;
    for (int h = 0; h < Hh; h++) {
        float x = qkv[((size_t)(b * TMAX + k + 1)) * 1152 + 768 + h * 64 + tid];
        red[tid] = x * x; __syncthreads();
        for (int st = 32; st > 0; st >>= 1) { if (tid < st) red[tid] += red[tid + st]; __syncthreads(); }
        if (tid == 0) {
            float nrm = sqrtf(red[0]);
            float p = g_S[((size_t)(b * Hh + h)) * TMAX * TMAX + (k + 1)];
            racc += p * nrm;
        }
        __syncthreads();
    }
    if (tid == 0) g_raw[b * NPATCH + k] = racc;
}

// ---------------- mass[b] = sum_k raw[b,k] ----------------
__global__ void k_mass() {
    int ntok = g_Ntok;
    int b = blockIdx.x;
    __shared__ float red[256];
    int tid = threadIdx.x;
    float s = 0.f;
    for (int k = tid; k < ntok - 1; k += 256) s += g_raw[b * NPATCH + k];
    red[tid] = s; __syncthreads();
    for (int st = 128; st > 0; st >>= 1) { if (tid < st) red[tid] += red[tid + st]; __syncthreads(); }
    if (tid == 0) g_mass[b] = red[0];
}

// ---------------- scores[k] = mean_b raw/(mass+eps) ----------------
__global__ void k_scores() {
    int ntok = g_Ntok;
    int k = blockIdx.x * 256 + threadIdx.x;
    if (k >= ntok - 1) return;
    float s = 0.f;
    #pragma unroll
    for (int b = 0; b < Bc; b++) s += g_raw[b * NPATCH + k] / (g_mass[b] + 1e-6f);
    g_scores[k] = s / 8.f;
}

// ---------------- controller: compute keep ratio / N_next ----------------
__global__ void k_controller() {
    int ntok = g_Ntok, Np = ntok - 1;
    if (Np > 16) {
        float mr = 0.f;
        for (int b = 0; b < Bc; b++) {
            float rb = 0.f;
            for (int h = 0; h < Hh; h++) rb += g_rho_bh[b * Hh + h];
            mr += rb / 6.f;
        }
        mr /= 8.f;
        int nn;
        if (g_hasprev) {
            float md = 0.f;
            for (int b = 0; b < Bc; b++)
                md += fabsf(g_mass[b] - g_prevmass[b]) / (g_prevmass[b] + 1e-6f);
            md /= 8.f;
            float kr = 1.0f - 0.1f * (mr + md);
            kr = fminf(fmaxf(kr, 0.f), 1.f);
            nn = (int)((double)Np * (double)kr);
            if (nn < 16) nn = 16;
        } else {
            nn = Np;
        }
        for (int b = 0; b < Bc; b++) g_prevmass[b] = g_mass[b];
        g_hasprev = 1;
        g_Nnext = nn;
    } else {
        g_Nnext = Np;
    }
}

// ---------------- top-k selection + sorted keep list (exact lax.top_k ties) ------
__global__ void k_topk() {
    __shared__ float sc[NPATCH];
    __shared__ unsigned char kp[NPATCH];
    int ntok = g_Ntok, Np = ntok - 1, nn = g_Nnext;
    int k = threadIdx.x;
    if (k < Np) sc[k] = g_scores[k];
    __syncthreads();
    int keep = 0;
    if (k < Np) {
        float s = sc[k];
        int rank = 0;
        for (int j = 0; j < Np; j++) {
            float o = sc[j];
            rank += (o > s) || (o == s && j < k);
        }
        keep = (rank < nn);
    }
    kp[k] = (unsigned char)keep;
    __syncthreads();
    if (keep) {
        int pos = 0;
        for (int j = 0; j < k; j++) pos += kp[j];
        g_keep[pos + 1] = k + 1;
    }
    if (k == 0) { g_keep[0] = 0; g_Ntok = nn + 1; }
}

// ---------------- gather: dst[b,i,:] = src[b,keep[i],:] ----------------
__global__ void k_gather(const float* __restrict__ src, float* __restrict__ dst) {
    int ntok = g_Ntok;           // updated value
    int t = blockIdx.x; if (t >= ntok) return;
    int b = blockIdx.y, d = threadIdx.x;
    int st = g_keep[t];
    dst[((size_t)(b * TMAX + t)) * Dm + d] = src[((size_t)(b * TMAX + st)) * Dm + d];
}

// ---------------- classification head (CLS token only) ----------------
__global__ void k_head(const float* __restrict__ xn, const float* __restrict__ W,
                       const float* __restrict__ bb, float* __restrict__ out) {
    int n = blockIdx.x * 128 + threadIdx.x;
    int b = blockIdx.y;
    if (n >= NCLSD) return;
    const float* xr = xn + (size_t)b * TMAX * Dm;   // token 0
    float s = 0.f;
    for (int k = 0; k < Dm; k++) s += xr[k] * W[(size_t)k * NCLSD + n];
    out[b * NCLSD + n] = s + bb[n];
}

// ================================= host =================================
extern "C" void kernel_launch(void* const* d_in, const int* in_sizes, int n_in,
                              void* d_out, int out_size) {
    const float* x       = (const float*)d_in[0];
    const float* patch_w = (const float*)d_in[1];
    const float* patch_b = (const float*)d_in[2];
    const float* cls     = (const float*)d_in[3];
    const float* pos     = (const float*)d_in[4];
    const float* ln1_s   = (const float*)d_in[5];
    const float* ln1_b   = (const float*)d_in[6];
    const float* qkv_w   = (const float*)d_in[7];
    const float* qkv_b   = (const float*)d_in[8];
    const float* proj_w  = (const float*)d_in[9];
    const float* proj_b  = (const float*)d_in[10];
    const float* ln2_s   = (const float*)d_in[11];
    const float* ln2_b   = (const float*)d_in[12];
    const float* fc1_w   = (const float*)d_in[13];
    const float* fc1_b   = (const float*)d_in[14];
    const float* fc2_w   = (const float*)d_in[15];
    const float* fc2_b   = (const float*)d_in[16];
    const float* norm_s  = (const float*)d_in[17];
    const float* norm_b  = (const float*)d_in[18];
    const float* head_w  = (const float*)d_in[19];
    const float* head_b  = (const float*)d_in[20];
    float* out = (float*)d_out;

    float *pPatches, *pXA, *pXB, *pXn, *pQkv, *pAo, *pHid;
    cudaGetSymbolAddress((void**)&pPatches, g_patches);
    cudaGetSymbolAddress((void**)&pXA,  g_xA);
    cudaGetSymbolAddress((void**)&pXB,  g_xB);
    cudaGetSymbolAddress((void**)&pXn,  g_xn);
    cudaGetSymbolAddress((void**)&pQkv, g_qkv);
    cudaGetSymbolAddress((void**)&pAo,  g_ao);
    cudaGetSymbolAddress((void**)&pHid, g_hid);

    k_init<<<1, 1>>>();
    k_patchify<<<dim3(NPATCH, Bc), 256>>>(x);
    // tok = patches @ patch_w + patch_b  (into g_hid scratch, rows=576)
    k_gemm<<<dim3(Dm / 64, NPATCH / 64, Bc), 256>>>(
        pPatches, NPATCH, 768, patch_w, Dm, patch_b, (const float*)0, pHid, 0, 0, NPATCH);
    k_embed<<<dim3(TMAX, Bc), Dm>>>(cls, pos, pHid, pXA);

    float* src = pXA;
    float* dst = pXB;
    const int tTiles = (TMAX + 63) / 64;   // 10
    for (int l = 0; l < Lc; l++) {
        k_ln<<<dim3(TMAX, Bc), 128>>>(src, ln1_s + l * Dm, ln1_b + l * Dm, pXn, 1, 0);
        k_gemm<<<dim3(1152 / 64, tTiles, Bc), 256>>>(
            pXn, TMAX, Dm, qkv_w + (size_t)l * Dm * 1152, 1152, qkv_b + l * 1152,
            (const float*)0, pQkv, 0, 1, 0);
        k_qk<<<dim3(19, 19, Bc * Hh), 256>>>(pQkv);
        k_softmax<<<dim3(TMAX, Bc * Hh), 256>>>();
        k_ent<<<Bc * Hh, 256>>>();
        k_av<<<dim3(19, Hh, Bc), 256>>>(pQkv);
        k_raw<<<dim3(NPATCH, Bc), 64>>>(pQkv);
        k_mass<<<Bc, 256>>>();
        k_gemm<<<dim3(Dm / 64, tTiles, Bc), 256>>>(
            pAo, TMAX, Dm, proj_w + (size_t)l * Dm * Dm, Dm, proj_b + l * Dm,
            src, src, 0, 1, 0);
        k_ln<<<dim3(TMAX, Bc), 128>>>(src, ln2_s + l * Dm, ln2_b + l * Dm, pXn, 1, 0);
        k_gemm<<<dim3(MLPD / 64, tTiles, Bc), 256>>>(
            pXn, TMAX, Dm, fc1_w + (size_t)l * Dm * MLPD, MLPD, fc1_b + l * MLPD,
            (const float*)0, pHid, 1, 1, 0);
        k_gemm<<<dim3(Dm / 64, tTiles, Bc), 256>>>(
            pHid, TMAX, MLPD, fc2_w + (size_t)l * MLPD * Dm, Dm, fc2_b + l * Dm,
            src, src, 0, 1, 0);
        k_scores<<<3, 256>>>();
        k_controller<<<1, 1>>>();
        k_topk<<<1, NPATCH>>>();
        k_gather<<<dim3(TMAX, Bc), Dm>>>(src, dst);
        float* tmp = src; src = dst; dst = tmp;
    }

    // final LN on CLS token only, then head
    k_ln<<<dim3(1, Bc), 128>>>(src, norm_s, norm_b, pXn, 0, 1);
    k_head<<<dim3((NCLSD + 127) / 128, Bc), 128>>>(pXn, head_w, head_b, out);
}

// round 2
// speedup vs baseline: 1.1845x; 1.1845x over previous
#include <cuda_runtime.h>
#include <math.h>

#define Bc 8
#define Dm 384
#define Hh 6
#define HD 64
#define Lc 12
#define MLPD 1536
#define NCLSD 1000
#define TMAX 577
#define NPATCH 576
#define GG 24
#define SP 640   // padded row pitch for attention matrix

// ---------------- scratch (device globals; no allocation allowed) ----------------
__device__ float g_patches[Bc * NPATCH * 768];
__device__ float g_xA[Bc * TMAX * Dm];
__device__ float g_xB[Bc * TMAX * Dm];
__device__ float g_xn[Bc * TMAX * Dm];
__device__ float g_qkv[Bc * TMAX * 3 * Dm];
__device__ float g_S[(size_t)Bc * Hh * TMAX * SP];   // ~70.9 MB attention matrix (pitched)
__device__ float g_ao[Bc * TMAX * Dm];
__device__ float g_hid[Bc * TMAX * MLPD];
__device__ float g_rho_bh[Bc * Hh];
__device__ float g_raw[Bc * NPATCH];
__device__ float g_mass[Bc];
__device__ float g_prevmass[Bc];
__device__ float g_scores[NPATCH];
__device__ int   g_keep[TMAX];
__device__ int   g_Ntok;
__device__ int   g_Nnext;
__device__ int   g_hasprev;

// ---------------- init ----------------
__global__ void k_init() { g_Ntok = TMAX; g_hasprev = 0; }

// ---------------- patchify: x[B,3,384,384] -> patches[B,576,768] ----------------
__global__ void k_patchify(const float* __restrict__ x) {
    int p = blockIdx.x, b = blockIdx.y;
    int gy = p / GG, gx = p % GG;
    for (int f = threadIdx.x; f < 768; f += blockDim.x) {
        int c = f >> 8, r = (f >> 4) & 15, cc = f & 15;
        g_patches[((size_t)(b * NPATCH + p)) * 768 + f] =
            x[(((size_t)(b * 3 + c)) * 384 + gy * 16 + r) * 384 + gx * 16 + cc];
    }
}

// ---------------- 128x128x8 fp32 GEMM: C = act(A@W + bias) (+res) ----------------
// A: [B][rows][K] (rows = stride), W: [K][N], N % 128 == 0, K % 8 == 0
__global__ void __launch_bounds__(256) k_gemm(
    const float* __restrict__ A, int rows, int K,
    const float* __restrict__ W, int N,
    const float* __restrict__ bias,
    const float* __restrict__ res,
    float* __restrict__ C,
    int act, int useDyn, int ntokFixed)
{
    int ntok = useDyn ? g_Ntok : ntokFixed;
    int b  = blockIdx.z;
    int t0 = blockIdx.y * 128;
    int n0 = blockIdx.x * 128;
    if (t0 >= ntok) return;

    __shared__ float As[8][128];
    __shared__ float Bs[8][128];
    int tid = threadIdx.x;
    int tx = tid & 15, ty = tid >> 4;
    const float* Ab = A + (size_t)b * rows * K;

    // load mappings
    int arow = tid >> 1;            // 0..127
    int acol = (tid & 1) * 4;       // 0 or 4
    int brow = tid >> 5;            // 0..7
    int bcol = (tid & 31) * 4;      // 0..124
    int ta = t0 + arow;
    bool avalid = (ta < rows);
    const float* aptr = Ab + (size_t)(avalid ? ta : 0) * K + acol;
    const float* bptr = W + (size_t)brow * N + n0 + bcol;

    float acc[8][8] = {};
    float4 av = avalid ? *(const float4*)(aptr) : make_float4(0.f, 0.f, 0.f, 0.f);
    float4 bv = *(const float4*)(bptr);

    for (int k0 = 0; k0 < K; k0 += 8) {
        As[acol + 0][arow] = av.x; As[acol + 1][arow] = av.y;
        As[acol + 2][arow] = av.z; As[acol + 3][arow] = av.w;
        *(float4*)&Bs[brow][bcol] = bv;
        __syncthreads();
        if (k0 + 8 < K) {
            av = avalid ? *(const float4*)(aptr + k0 + 8) : make_float4(0.f, 0.f, 0.f, 0.f);
            bv = *(const float4*)(bptr + (size_t)(k0 + 8) * N);
        }
        #pragma unroll
        for (int kk = 0; kk < 8; kk++) {
            float4 a0 = *(float4*)&As[kk][ty * 4];
            float4 a1 = *(float4*)&As[kk][ty * 4 + 64];
            float4 b0 = *(float4*)&Bs[kk][tx * 4];
            float4 b1 = *(float4*)&Bs[kk][tx * 4 + 64];
            float am[8] = {a0.x, a0.y, a0.z, a0.w, a1.x, a1.y, a1.z, a1.w};
            float bn[8] = {b0.x, b0.y, b0.z, b0.w, b1.x, b1.y, b1.z, b1.w};
            #pragma unroll
            for (int i = 0; i < 8; i++)
                #pragma unroll
                for (int j = 0; j < 8; j++)
                    acc[i][j] += am[i] * bn[j];
        }
        __syncthreads();
    }

    #pragma unroll
    for (int i = 0; i < 8; i++) {
        int m = t0 + ((i < 4) ? (ty * 4 + i) : (ty * 4 + i - 4 + 64));
        if (m >= rows) continue;
        float* Crow = C + ((size_t)b * rows + m) * N;
        const float* Rrow = res ? res + ((size_t)b * rows + m) * N : (const float*)0;
        #pragma unroll
        for (int j = 0; j < 8; j++) {
            int n = n0 + ((j < 4) ? (tx * 4 + j) : (tx * 4 + j - 4 + 64));
            float v = acc[i][j] + bias[n];
            if (act == 1) v = 0.5f * v * (1.f + erff(v * 0.70710678118654752f));
            if (Rrow) v += Rrow[n];
            Crow[n] = v;
        }
    }
}

// ---------------- embed: xcur = [cls | tok] + pos (float4) ----------------
__global__ void k_embed(const float* __restrict__ cls, const float* __restrict__ pos,
                        const float* __restrict__ tok, float* __restrict__ X) {
    int t = blockIdx.x, b = blockIdx.y, d = threadIdx.x;   // d: 0..95 float4 lanes
    const float4* src = (t == 0) ? (const float4*)cls
                                 : (const float4*)&tok[((size_t)(b * NPATCH + t - 1)) * Dm];
    float4 v = src[d];
    float4 p = ((const float4*)&pos[(size_t)t * Dm])[d];
    v.x += p.x; v.y += p.y; v.z += p.z; v.w += p.w;
    ((float4*)&X[((size_t)(b * TMAX + t)) * Dm])[d] = v;
}

// ---------------- LayerNorm ----------------
__global__ void k_ln(const float* __restrict__ X, const float* __restrict__ s,
                     const float* __restrict__ bb, float* __restrict__ O,
                     int useDyn, int ntokFixed) {
    int ntok = useDyn ? g_Ntok : ntokFixed;
    int t = blockIdx.x; if (t >= ntok) return;
    int b = blockIdx.y;
    const float* xr = X + ((size_t)(b * TMAX + t)) * Dm;
    __shared__ float red[128];
    int tid = threadIdx.x;
    float v0 = xr[tid], v1 = xr[tid + 128], v2 = xr[tid + 256];
    red[tid] = v0 + v1 + v2; __syncthreads();
    for (int st = 64; st > 0; st >>= 1) { if (tid < st) red[tid] += red[tid + st]; __syncthreads(); }
    float mean = red[0] / 384.f; __syncthreads();
    float d0 = v0 - mean, d1 = v1 - mean, d2 = v2 - mean;
    red[tid] = d0 * d0 + d1 * d1 + d2 * d2; __syncthreads();
    for (int st = 64; st > 0; st >>= 1) { if (tid < st) red[tid] += red[tid + st]; __syncthreads(); }
    float var = red[0] / 384.f;
    float inv = 1.f / sqrtf(var + 1e-5f);
    float* orow = O + ((size_t)(b * TMAX + t)) * Dm;
    orow[tid]       = d0 * inv * s[tid]       + bb[tid];
    orow[tid + 128] = d1 * inv * s[tid + 128] + bb[tid + 128];
    orow[tid + 256] = d2 * inv * s[tid + 256] + bb[tid + 256];
}

// ---------------- attention scores S = Q K^T * hd^-0.5 (64x64 tiles) ----------------
__global__ void __launch_bounds__(256) k_qk(const float* __restrict__ qkv) {
    int ntok = g_Ntok;
    int b = blockIdx.z / Hh, h = blockIdx.z % Hh;
    int q0 = blockIdx.y * 64, k0 = blockIdx.x * 64;
    if (q0 >= ntok || k0 >= ntok) return;
    __shared__ float Qs[64][65];
    __shared__ float Ks[64][65];
    int tid = threadIdx.x;
    #pragma unroll
    for (int i = 0; i < 4; i++) {
        int idx = tid + i * 256;
        int r = idx >> 4, d4 = (idx & 15) * 4;
        int tq = q0 + r, tk = k0 + r;
        float4 qv = (tq < ntok) ? *(const float4*)&qkv[((size_t)(b * TMAX + tq)) * 1152 + h * 64 + d4]
                                : make_float4(0.f, 0.f, 0.f, 0.f);
        float4 kv = (tk < ntok) ? *(const float4*)&qkv[((size_t)(b * TMAX + tk)) * 1152 + 384 + h * 64 + d4]
                                : make_float4(0.f, 0.f, 0.f, 0.f);
        Qs[r][d4] = qv.x; Qs[r][d4 + 1] = qv.y; Qs[r][d4 + 2] = qv.z; Qs[r][d4 + 3] = qv.w;
        Ks[r][d4] = kv.x; Ks[r][d4 + 1] = kv.y; Ks[r][d4 + 2] = kv.z; Ks[r][d4 + 3] = kv.w;
    }
    __syncthreads();
    int tx = tid & 15, ty = tid >> 4;
    float acc[4][4] = {};
    #pragma unroll 8
    for (int d = 0; d < 64; d++) {
        float a0 = Qs[ty * 4 + 0][d], a1 = Qs[ty * 4 + 1][d];
        float a2 = Qs[ty * 4 + 2][d], a3 = Qs[ty * 4 + 3][d];
        float b0 = Ks[tx * 4 + 0][d], b1 = Ks[tx * 4 + 1][d];
        float b2 = Ks[tx * 4 + 2][d], b3 = Ks[tx * 4 + 3][d];
        acc[0][0] += a0 * b0; acc[0][1] += a0 * b1; acc[0][2] += a0 * b2; acc[0][3] += a0 * b3;
        acc[1][0] += a1 * b0; acc[1][1] += a1 * b1; acc[1][2] += a1 * b2; acc[1][3] += a1 * b3;
        acc[2][0] += a2 * b0; acc[2][1] += a2 * b1; acc[2][2] += a2 * b2; acc[2][3] += a2 * b3;
        acc[3][0] += a3 * b0; acc[3][1] += a3 * b1; acc[3][2] += a3 * b2; acc[3][3] += a3 * b3;
    }
    float* Sb = g_S + ((size_t)(b * Hh + h)) * TMAX * SP;
    #pragma unroll
    for (int i = 0; i < 4; i++) {
        int q = q0 + ty * 4 + i;
        if (q >= ntok) continue;
        #pragma unroll
        for (int j = 0; j < 4; j++) {
            int k = k0 + tx * 4 + j;
            if (k < ntok) Sb[(size_t)q * SP + k] = acc[i][j] * 0.125f;
        }
    }
}

// ---------------- softmax rows (in place, pitched) ----------------
__global__ void k_softmax() {
    int ntok = g_Ntok;
    int q = blockIdx.x; if (q >= ntok) return;
    int bh = blockIdx.y;
    float* row = g_S + ((size_t)bh * TMAX + q) * SP;
    __shared__ float red[256];
    int tid = threadIdx.x;
    float v[3]; float mx = -1e30f;
    #pragma unroll
    for (int i = 0; i < 3; i++) {
        int k = tid + 256 * i;
        v[i] = (k < ntok) ? row[k] : -1e30f;
        mx = fmaxf(mx, v[i]);
    }
    red[tid] = mx; __syncthreads();
    for (int st = 128; st > 0; st >>= 1) { if (tid < st) red[tid] = fmaxf(red[tid], red[tid + st]); __syncthreads(); }
    mx = red[0]; __syncthreads();
    float sm = 0.f;
    #pragma unroll
    for (int i = 0; i < 3; i++) {
        int k = tid + 256 * i;
        v[i] = (k < ntok) ? expf(v[i] - mx) : 0.f;
        sm += v[i];
    }
    red[tid] = sm; __syncthreads();
    for (int st = 128; st > 0; st >>= 1) { if (tid < st) red[tid] += red[tid + st]; __syncthreads(); }
    float inv = 1.f / red[0];
    #pragma unroll
    for (int i = 0; i < 3; i++) {
        int k = tid + 256 * i;
        if (k < ntok) row[k] = v[i] * inv;
    }
}

// ---------------- out = attn @ V (64-row tiles, full d=64) ----------------
__global__ void __launch_bounds__(256) k_av(const float* __restrict__ qkv) {
    int ntok = g_Ntok;
    int q0 = blockIdx.x * 64; if (q0 >= ntok) return;
    int h = blockIdx.y, b = blockIdx.z;
    __shared__ float Ps[64][65];
    __shared__ float Vs[64][65];
    int tid = threadIdx.x, tx = tid & 15, ty = tid >> 4;
    float acc[4][4] = {};
    const float* Sb = g_S + ((size_t)(b * Hh + h)) * TMAX * SP;
    for (int k0 = 0; k0 < ntok; k0 += 64) {
        #pragma unroll
        for (int i = 0; i < 4; i++) {
            int idx = tid + i * 256;
            int r = idx >> 4, c4 = (idx & 15) * 4;
            int q = q0 + r;
            // P rows beyond ntok -> zero; cols beyond ntok hold stale-but-finite
            // values which are annihilated by zeroed V rows below.
            float4 pv = (q < ntok) ? *(const float4*)&Sb[(size_t)q * SP + k0 + c4]
                                   : make_float4(0.f, 0.f, 0.f, 0.f);
            Ps[r][c4] = pv.x; Ps[r][c4 + 1] = pv.y; Ps[r][c4 + 2] = pv.z; Ps[r][c4 + 3] = pv.w;
            int k = k0 + r;
            float4 vv = (k < ntok) ? *(const float4*)&qkv[((size_t)(b * TMAX + k)) * 1152 + 768 + h * 64 + c4]
                                   : make_float4(0.f, 0.f, 0.f, 0.f);
            Vs[r][c4] = vv.x; Vs[r][c4 + 1] = vv.y; Vs[r][c4 + 2] = vv.z; Vs[r][c4 + 3] = vv.w;
        }
        __syncthreads();
        #pragma unroll 8
        for (int kk = 0; kk < 64; kk++) {
            float a0 = Ps[ty * 4 + 0][kk], a1 = Ps[ty * 4 + 1][kk];
            float a2 = Ps[ty * 4 + 2][kk], a3 = Ps[ty * 4 + 3][kk];
            float b0 = Vs[kk][tx * 4 + 0], b1 = Vs[kk][tx * 4 + 1];
            float b2 = Vs[kk][tx * 4 + 2], b3 = Vs[kk][tx * 4 + 3];
            acc[0][0] += a0 * b0; acc[0][1] += a0 * b1; acc[0][2] += a0 * b2; acc[0][3] += a0 * b3;
            acc[1][0] += a1 * b0; acc[1][1] += a1 * b1; acc[1][2] += a1 * b2; acc[1][3] += a1 * b3;
            acc[2][0] += a2 * b0; acc[2][1] += a2 * b1; acc[2][2] += a2 * b2; acc[2][3] += a2 * b3;
            acc[3][0] += a3 * b0; acc[3][1] += a3 * b1; acc[3][2] += a3 * b2; acc[3][3] += a3 * b3;
        }
        __syncthreads();
    }
    #pragma unroll
    for (int i = 0; i < 4; i++) {
        int q = q0 + ty * 4 + i;
        if (q >= ntok) continue;
        #pragma unroll
        for (int j = 0; j < 4; j++)
            g_ao[((size_t)(b * TMAX + q)) * Dm + h * 64 + tx * 4 + j] = acc[i][j];
    }
}

// ---------------- CLS entropy per (b,h) ----------------
__global__ void k_ent() {
    int ntok = g_Ntok;
    int bh = blockIdx.x;
    const float* row = g_S + ((size_t)bh) * TMAX * SP;   // q = 0
    __shared__ float red[256];
    int tid = threadIdx.x;
    float s = 0.f;
    for (int k = tid; k < ntok; k += 256) { float p = row[k]; s += p * logf(p + 1e-6f); }
    red[tid] = s; __syncthreads();
    for (int st = 128; st > 0; st >>= 1) { if (tid < st) red[tid] += red[tid + st]; __syncthreads(); }
    if (tid == 0) g_rho_bh[bh] = -red[0] / logf((float)ntok);
}

// ---------------- raw[b,k] = sum_h attn[b,h,0,k+1] * ||v[b,h,k+1]|| ----------------
__global__ void k_raw(const float* __restrict__ qkv) {
    int ntok = g_Ntok;
    int k = blockIdx.x, b = blockIdx.y;
    if (k + 1 >= ntok) return;
    __shared__ float red[64];
    __shared__ float racc;
    int tid = threadIdx.x;
    if (tid == 0) racc = 0.f;
    for (int h = 0; h < Hh; h++) {
        float x = qkv[((size_t)(b * TMAX + k + 1)) * 1152 + 768 + h * 64 + tid];
        red[tid] = x * x; __syncthreads();
        for (int st = 32; st > 0; st >>= 1) { if (tid < st) red[tid] += red[tid + st]; __syncthreads(); }
        if (tid == 0) {
            float nrm = sqrtf(red[0]);
            float p = g_S[((size_t)(b * Hh + h)) * TMAX * SP + (k + 1)];
            racc += p * nrm;
        }
        __syncthreads();
    }
    if (tid == 0) g_raw[b * NPATCH + k] = racc;
}

// ---------------- mass[b] = sum_k raw[b,k] ----------------
__global__ void k_mass() {
    int ntok = g_Ntok;
    int b = blockIdx.x;
    __shared__ float red[256];
    int tid = threadIdx.x;
    float s = 0.f;
    for (int k = tid; k < ntok - 1; k += 256) s += g_raw[b * NPATCH + k];
    red[tid] = s; __syncthreads();
    for (int st = 128; st > 0; st >>= 1) { if (tid < st) red[tid] += red[tid + st]; __syncthreads(); }
    if (tid == 0) g_mass[b] = red[0];
}

// ---------------- scores[k] = mean_b raw/(mass+eps) ----------------
__global__ void k_scores() {
    int ntok = g_Ntok;
    int k = blockIdx.x * 256 + threadIdx.x;
    if (k >= ntok - 1) return;
    float s = 0.f;
    #pragma unroll
    for (int b = 0; b < Bc; b++) s += g_raw[b * NPATCH + k] / (g_mass[b] + 1e-6f);
    g_scores[k] = s / 8.f;
}

// ---------------- controller ----------------
__global__ void k_controller() {
    int ntok = g_Ntok, Np = ntok - 1;
    if (Np > 16) {
        float mr = 0.f;
        for (int b = 0; b < Bc; b++) {
            float rb = 0.f;
            for (int h = 0; h < Hh; h++) rb += g_rho_bh[b * Hh + h];
            mr += rb / 6.f;
        }
        mr /= 8.f;
        int nn;
        if (g_hasprev) {
            float md = 0.f;
            for (int b = 0; b < Bc; b++)
                md += fabsf(g_mass[b] - g_prevmass[b]) / (g_prevmass[b] + 1e-6f);
            md /= 8.f;
            float kr = 1.0f - 0.1f * (mr + md);
            kr = fminf(fmaxf(kr, 0.f), 1.f);
            nn = (int)((double)Np * (double)kr);
            if (nn < 16) nn = 16;
        } else {
            nn = Np;
        }
        for (int b = 0; b < Bc; b++) g_prevmass[b] = g_mass[b];
        g_hasprev = 1;
        g_Nnext = nn;
    } else {
        g_Nnext = Np;
    }
}

// ---------------- top-k selection + sorted keep list ----------------
__global__ void k_topk() {
    __shared__ float sc[NPATCH];
    __shared__ unsigned char kp[NPATCH];
    int ntok = g_Ntok, Np = ntok - 1, nn = g_Nnext;
    int k = threadIdx.x;
    if (k < Np) sc[k] = g_scores[k];
    __syncthreads();
    int keep = 0;
    if (k < Np) {
        float s = sc[k];
        int rank = 0;
        for (int j = 0; j < Np; j++) {
            float o = sc[j];
            rank += (o > s) || (o == s && j < k);
        }
        keep = (rank < nn);
    }
    kp[k] = (unsigned char)keep;
    __syncthreads();
    if (keep) {
        int pos = 0;
        for (int j = 0; j < k; j++) pos += kp[j];
        g_keep[pos + 1] = k + 1;
    }
    if (k == 0) { g_keep[0] = 0; g_Ntok = nn + 1; }
}

// ---------------- gather: dst[b,i,:] = src[b,keep[i],:] (float4) ----------------
__global__ void k_gather(const float* __restrict__ src, float* __restrict__ dst) {
    int ntok = g_Ntok;
    int t = blockIdx.x; if (t >= ntok) return;
    int b = blockIdx.y, d = threadIdx.x;    // 0..95
    int st = g_keep[t];
    ((float4*)&dst[((size_t)(b * TMAX + t)) * Dm])[d] =
        ((const float4*)&src[((size_t)(b * TMAX + st)) * Dm])[d];
}

// ---------------- classification head (CLS token only) ----------------
__global__ void k_head(const float* __restrict__ xn, const float* __restrict__ W,
                       const float* __restrict__ bb, float* __restrict__ out) {
    int n = blockIdx.x * 128 + threadIdx.x;
    int b = blockIdx.y;
    if (n >= NCLSD) return;
    const float* xr = xn + (size_t)b * TMAX * Dm;   // token 0
    float s = 0.f;
    for (int k = 0; k < Dm; k++) s += xr[k] * W[(size_t)k * NCLSD + n];
    out[b * NCLSD + n] = s + bb[n];
}

// ================================= host =================================
extern "C" void kernel_launch(void* const* d_in, const int* in_sizes, int n_in,
                              void* d_out, int out_size) {
    const float* x       = (const float*)d_in[0];
    const float* patch_w = (const float*)d_in[1];
    const float* patch_b = (const float*)d_in[2];
    const float* cls     = (const float*)d_in[3];
    const float* pos     = (const float*)d_in[4];
    const float* ln1_s   = (const float*)d_in[5];
    const float* ln1_b   = (const float*)d_in[6];
    const float* qkv_w   = (const float*)d_in[7];
    const float* qkv_b   = (const float*)d_in[8];
    const float* proj_w  = (const float*)d_in[9];
    const float* proj_b  = (const float*)d_in[10];
    const float* ln2_s   = (const float*)d_in[11];
    const float* ln2_b   = (const float*)d_in[12];
    const float* fc1_w   = (const float*)d_in[13];
    const float* fc1_b   = (const float*)d_in[14];
    const float* fc2_w   = (const float*)d_in[15];
    const float* fc2_b   = (const float*)d_in[16];
    const float* norm_s  = (const float*)d_in[17];
    const float* norm_b  = (const float*)d_in[18];
    const float* head_w  = (const float*)d_in[19];
    const float* head_b  = (const float*)d_in[20];
    float* out = (float*)d_out;

    float *pPatches, *pXA, *pXB, *pXn, *pQkv, *pAo, *pHid;
    cudaGetSymbolAddress((void**)&pPatches, g_patches);
    cudaGetSymbolAddress((void**)&pXA,  g_xA);
    cudaGetSymbolAddress((void**)&pXB,  g_xB);
    cudaGetSymbolAddress((void**)&pXn,  g_xn);
    cudaGetSymbolAddress((void**)&pQkv, g_qkv);
    cudaGetSymbolAddress((void**)&pAo,  g_ao);
    cudaGetSymbolAddress((void**)&pHid, g_hid);

    k_init<<<1, 1>>>();
    k_patchify<<<dim3(NPATCH, Bc), 256>>>(x);
    k_gemm<<<dim3(Dm / 128, (NPATCH + 127) / 128, Bc), 256>>>(
        pPatches, NPATCH, 768, patch_w, Dm, patch_b, (const float*)0, pHid, 0, 0, NPATCH);
    k_embed<<<dim3(TMAX, Bc), 96>>>(cls, pos, pHid, pXA);

    float* src = pXA;
    float* dst = pXB;
    const int tTiles = (TMAX + 127) / 128;   // 5
    const int aTiles = (TMAX + 63) / 64;     // 10
    for (int l = 0; l < Lc; l++) {
        k_ln<<<dim3(TMAX, Bc), 128>>>(src, ln1_s + l * Dm, ln1_b + l * Dm, pXn, 1, 0);
        k_gemm<<<dim3(1152 / 128, tTiles, Bc), 256>>>(
            pXn, TMAX, Dm, qkv_w + (size_t)l * Dm * 1152, 1152, qkv_b + l * 1152,
            (const float*)0, pQkv, 0, 1, 0);
        k_qk<<<dim3(aTiles, aTiles, Bc * Hh), 256>>>(pQkv);
        k_softmax<<<dim3(TMAX, Bc * Hh), 256>>>();
        k_ent<<<Bc * Hh, 256>>>();
        k_av<<<dim3(aTiles, Hh, Bc), 256>>>(pQkv);
        k_raw<<<dim3(NPATCH, Bc), 64>>>(pQkv);
        k_mass<<<Bc, 256>>>();
        k_gemm<<<dim3(Dm / 128, tTiles, Bc), 256>>>(
            pAo, TMAX, Dm, proj_w + (size_t)l * Dm * Dm, Dm, proj_b + l * Dm,
            src, src, 0, 1, 0);
        k_ln<<<dim3(TMAX, Bc), 128>>>(src, ln2_s + l * Dm, ln2_b + l * Dm, pXn, 1, 0);
        k_gemm<<<dim3(MLPD / 128, tTiles, Bc), 256>>>(
            pXn, TMAX, Dm, fc1_w + (size_t)l * Dm * MLPD, MLPD, fc1_b + l * MLPD,
            (const float*)0, pHid, 1, 1, 0);
        k_gemm<<<dim3(Dm / 128, tTiles, Bc), 256>>>(
            pHid, TMAX, MLPD, fc2_w + (size_t)l * MLPD * Dm, Dm, fc2_b + l * Dm,
            src, src, 0, 1, 0);
        k_scores<<<3, 256>>>();
        k_controller<<<1, 1>>>();
        k_topk<<<1, NPATCH>>>();
        k_gather<<<dim3(TMAX, Bc), 96>>>(src, dst);
        float* tmp = src; src = dst; dst = tmp;
    }

    k_ln<<<dim3(1, Bc), 128>>>(src, norm_s, norm_b, pXn, 0, 1);
    k_head<<<dim3((NCLSD + 127) / 128, Bc), 128>>>(pXn, head_w, head_b, out);
}

// round 3
// speedup vs baseline: 1.3224x; 1.1164x over previous
#include <cuda_runtime.h>
#include <math.h>

#define Bc 8
#define Dm 384
#define Hh 6
#define HD 64
#define Lc 12
#define MLPD 1536
#define NCLSD 1000
#define TMAX 577
#define NPATCH 576
#define GG 24
#define SP 640   // padded row pitch for attention matrix
#define MTOT (Bc * TMAX)   // 4616 flattened rows

// ---------------- scratch (device globals; no allocation allowed) ----------------
__device__ float g_patches[Bc * NPATCH * 768];
__device__ float g_xA[Bc * TMAX * Dm];
__device__ float g_xB[Bc * TMAX * Dm];
__device__ float g_xn[Bc * TMAX * Dm];
__device__ float g_qkv[Bc * TMAX * 3 * Dm];
__device__ float g_S[(size_t)Bc * Hh * TMAX * SP];   // pitched attention matrix
__device__ float g_ao[Bc * TMAX * Dm];
__device__ float g_hid[Bc * TMAX * MLPD];
__device__ float g_rho_bh[Bc * Hh];
__device__ float g_raw[Bc * NPATCH];
__device__ float g_prevmass[Bc];
__device__ int   g_keep[TMAX];
__device__ int   g_Ntok;
__device__ int   g_hasprev;

// ---------------- init ----------------
__global__ void k_init() { g_Ntok = TMAX; g_hasprev = 0; }

// ---------------- patchify ----------------
__global__ void k_patchify(const float* __restrict__ x) {
    int p = blockIdx.x, b = blockIdx.y;
    int gy = p / GG, gx = p % GG;
    for (int f = threadIdx.x; f < 768; f += blockDim.x) {
        int c = f >> 8, r = (f >> 4) & 15, cc = f & 15;
        g_patches[((size_t)(b * NPATCH + p)) * 768 + f] =
            x[(((size_t)(b * 3 + c)) * 384 + gy * 16 + r) * 384 + gx * 16 + cc];
    }
}

// ---------------- 64x64x8 fp32 GEMM, batch-flattened M ----------------
// A: [Mtotal][K] (row-major), W: [K][N], C/res: [Mtotal][N]. N%64==0, K%8==0.
// useDyn: rows are b*TMAX+t; tile skipped if every row has t >= g_Ntok.
__global__ void __launch_bounds__(256) k_gemm(
    const float* __restrict__ A, int Mtotal, int K,
    const float* __restrict__ W, int N,
    const float* __restrict__ bias,
    const float* __restrict__ res,
    float* __restrict__ C,
    int act, int useDyn)
{
    int m0 = blockIdx.y * 64;
    int n0 = blockIdx.x * 64;
    if (useDyn) {
        int ntok = g_Ntok;
        int tstart = m0 % TMAX;
        if (tstart >= ntok && tstart + 63 < TMAX) return;   // fully dead tile
    }
    __shared__ float As[8][64];
    __shared__ float Bs[8][68];
    int tid = threadIdx.x;
    int tx = tid & 15, ty = tid >> 4;

    bool isA = (tid < 128);
    int arow = (tid & 127) >> 1;
    int acol = (tid & 1) * 4;
    int brow = (tid & 127) >> 4;
    int bcol = (tid & 15) * 4;
    int am = m0 + arow;
    bool aval = isA && (am < Mtotal);
    const float* aptr = A + (size_t)(aval ? am : 0) * K + acol;
    const float* bptr = W + (size_t)brow * N + n0 + bcol;

    float4 pre;
    if (isA) pre = aval ? *(const float4*)aptr : make_float4(0.f, 0.f, 0.f, 0.f);
    else     pre = *(const float4*)bptr;

    float acc[4][4] = {};
    for (int k0 = 0; k0 < K; k0 += 8) {
        if (isA) {
            As[acol + 0][arow] = pre.x; As[acol + 1][arow] = pre.y;
            As[acol + 2][arow] = pre.z; As[acol + 3][arow] = pre.w;
        } else {
            *(float4*)&Bs[brow][bcol] = pre;
        }
        __syncthreads();
        if (k0 + 8 < K) {
            if (isA) pre = aval ? *(const float4*)(aptr + k0 + 8) : make_float4(0.f, 0.f, 0.f, 0.f);
            else     pre = *(const float4*)(bptr + (size_t)(k0 + 8) * N);
        }
        #pragma unroll
        for (int kk = 0; kk < 8; kk++) {
            float a0 = As[kk][ty * 4 + 0], a1 = As[kk][ty * 4 + 1];
            float a2 = As[kk][ty * 4 + 2], a3 = As[kk][ty * 4 + 3];
            float b0 = Bs[kk][tx * 4 + 0], b1 = Bs[kk][tx * 4 + 1];
            float b2 = Bs[kk][tx * 4 + 2], b3 = Bs[kk][tx * 4 + 3];
            acc[0][0] += a0 * b0; acc[0][1] += a0 * b1; acc[0][2] += a0 * b2; acc[0][3] += a0 * b3;
            acc[1][0] += a1 * b0; acc[1][1] += a1 * b1; acc[1][2] += a1 * b2; acc[1][3] += a1 * b3;
            acc[2][0] += a2 * b0; acc[2][1] += a2 * b1; acc[2][2] += a2 * b2; acc[2][3] += a2 * b3;
            acc[3][0] += a3 * b0; acc[3][1] += a3 * b1; acc[3][2] += a3 * b2; acc[3][3] += a3 * b3;
        }
        __syncthreads();
    }

    #pragma unroll
    for (int i = 0; i < 4; i++) {
        int m = m0 + ty * 4 + i;
        if (m >= Mtotal) continue;
        float* Crow = C + (size_t)m * N;
        const float* Rrow = res ? res + (size_t)m * N : (const float*)0;
        #pragma unroll
        for (int j = 0; j < 4; j++) {
            int n = n0 + tx * 4 + j;
            float v = acc[i][j] + bias[n];
            if (act == 1) v = 0.5f * v * (1.f + erff(v * 0.70710678118654752f));
            if (Rrow) v += Rrow[n];
            Crow[n] = v;
        }
    }
}

// ---------------- embed ----------------
__global__ void k_embed(const float* __restrict__ cls, const float* __restrict__ pos,
                        const float* __restrict__ tok, float* __restrict__ X) {
    int t = blockIdx.x, b = blockIdx.y, d = threadIdx.x;   // d: 0..95 float4 lanes
    const float4* src = (t == 0) ? (const float4*)cls
                                 : (const float4*)&tok[((size_t)(b * NPATCH + t - 1)) * Dm];
    float4 v = src[d];
    float4 p = ((const float4*)&pos[(size_t)t * Dm])[d];
    v.x += p.x; v.y += p.y; v.z += p.z; v.w += p.w;
    ((float4*)&X[((size_t)(b * TMAX + t)) * Dm])[d] = v;
}

// ---------------- LayerNorm ----------------
__global__ void k_ln(const float* __restrict__ X, const float* __restrict__ s,
                     const float* __restrict__ bb, float* __restrict__ O,
                     int useDyn, int ntokFixed) {
    int ntok = useDyn ? g_Ntok : ntokFixed;
    int t = blockIdx.x; if (t >= ntok) return;
    int b = blockIdx.y;
    const float* xr = X + ((size_t)(b * TMAX + t)) * Dm;
    __shared__ float red[128];
    int tid = threadIdx.x;
    float v0 = xr[tid], v1 = xr[tid + 128], v2 = xr[tid + 256];
    red[tid] = v0 + v1 + v2; __syncthreads();
    for (int st = 64; st > 0; st >>= 1) { if (tid < st) red[tid] += red[tid + st]; __syncthreads(); }
    float mean = red[0] / 384.f; __syncthreads();
    float d0 = v0 - mean, d1 = v1 - mean, d2 = v2 - mean;
    red[tid] = d0 * d0 + d1 * d1 + d2 * d2; __syncthreads();
    for (int st = 64; st > 0; st >>= 1) { if (tid < st) red[tid] += red[tid + st]; __syncthreads(); }
    float var = red[0] / 384.f;
    float inv = 1.f / sqrtf(var + 1e-5f);
    float* orow = O + ((size_t)(b * TMAX + t)) * Dm;
    orow[tid]       = d0 * inv * s[tid]       + bb[tid];
    orow[tid + 128] = d1 * inv * s[tid + 128] + bb[tid + 128];
    orow[tid + 256] = d2 * inv * s[tid + 256] + bb[tid + 256];
}

// ---------------- attention scores S = Q K^T * hd^-0.5 (64x64 tiles) ----------------
__global__ void __launch_bounds__(256) k_qk(const float* __restrict__ qkv) {
    int ntok = g_Ntok;
    int b = blockIdx.z / Hh, h = blockIdx.z % Hh;
    int q0 = blockIdx.y * 64, k0 = blockIdx.x * 64;
    if (q0 >= ntok || k0 >= ntok) return;
    __shared__ float Qs[64][65];
    __shared__ float Ks[64][65];
    int tid = threadIdx.x;
    #pragma unroll
    for (int i = 0; i < 4; i++) {
        int idx = tid + i * 256;
        int r = idx >> 4, d4 = (idx & 15) * 4;
        int tq = q0 + r, tk = k0 + r;
        float4 qv = (tq < ntok) ? *(const float4*)&qkv[((size_t)(b * TMAX + tq)) * 1152 + h * 64 + d4]
                                : make_float4(0.f, 0.f, 0.f, 0.f);
        float4 kv = (tk < ntok) ? *(const float4*)&qkv[((size_t)(b * TMAX + tk)) * 1152 + 384 + h * 64 + d4]
                                : make_float4(0.f, 0.f, 0.f, 0.f);
        Qs[r][d4] = qv.x; Qs[r][d4 + 1] = qv.y; Qs[r][d4 + 2] = qv.z; Qs[r][d4 + 3] = qv.w;
        Ks[r][d4] = kv.x; Ks[r][d4 + 1] = kv.y; Ks[r][d4 + 2] = kv.z; Ks[r][d4 + 3] = kv.w;
    }
    __syncthreads();
    int tx = tid & 15, ty = tid >> 4;
    float acc[4][4] = {};
    #pragma unroll 8
    for (int d = 0; d < 64; d++) {
        float a0 = Qs[ty * 4 + 0][d], a1 = Qs[ty * 4 + 1][d];
        float a2 = Qs[ty * 4 + 2][d], a3 = Qs[ty * 4 + 3][d];
        float b0 = Ks[tx * 4 + 0][d], b1 = Ks[tx * 4 + 1][d];
        float b2 = Ks[tx * 4 + 2][d], b3 = Ks[tx * 4 + 3][d];
        acc[0][0] += a0 * b0; acc[0][1] += a0 * b1; acc[0][2] += a0 * b2; acc[0][3] += a0 * b3;
        acc[1][0] += a1 * b0; acc[1][1] += a1 * b1; acc[1][2] += a1 * b2; acc[1][3] += a1 * b3;
        acc[2][0] += a2 * b0; acc[2][1] += a2 * b1; acc[2][2] += a2 * b2; acc[2][3] += a2 * b3;
        acc[3][0] += a3 * b0; acc[3][1] += a3 * b1; acc[3][2] += a3 * b2; acc[3][3] += a3 * b3;
    }
    float* Sb = g_S + ((size_t)(b * Hh + h)) * TMAX * SP;
    #pragma unroll
    for (int i = 0; i < 4; i++) {
        int q = q0 + ty * 4 + i;
        if (q >= ntok) continue;
        #pragma unroll
        for (int j = 0; j < 4; j++) {
            int k = k0 + tx * 4 + j;
            if (k < ntok) Sb[(size_t)q * SP + k] = acc[i][j] * 0.125f;
        }
    }
}

// ---------------- softmax rows (in place, pitched) + CLS entropy fused ----------------
__global__ void k_softmax() {
    int ntok = g_Ntok;
    int q = blockIdx.x; if (q >= ntok) return;
    int bh = blockIdx.y;
    float* row = g_S + ((size_t)bh * TMAX + q) * SP;
    __shared__ float red[256];
    int tid = threadIdx.x;
    float v[3]; float mx = -1e30f;
    #pragma unroll
    for (int i = 0; i < 3; i++) {
        int k = tid + 256 * i;
        v[i] = (k < ntok) ? row[k] : -1e30f;
        mx = fmaxf(mx, v[i]);
    }
    red[tid] = mx; __syncthreads();
    for (int st = 128; st > 0; st >>= 1) { if (tid < st) red[tid] = fmaxf(red[tid], red[tid + st]); __syncthreads(); }
    mx = red[0]; __syncthreads();
    float sm = 0.f;
    #pragma unroll
    for (int i = 0; i < 3; i++) {
        int k = tid + 256 * i;
        v[i] = (k < ntok) ? expf(v[i] - mx) : 0.f;
        sm += v[i];
    }
    red[tid] = sm; __syncthreads();
    for (int st = 128; st > 0; st >>= 1) { if (tid < st) red[tid] += red[tid + st]; __syncthreads(); }
    float inv = 1.f / red[0];
    #pragma unroll
    for (int i = 0; i < 3; i++) {
        int k = tid + 256 * i;
        if (k < ntok) row[k] = v[i] * inv;
    }
    if (q == 0) {   // fused CLS entropy
        __syncthreads();
        float e = 0.f;
        #pragma unroll
        for (int i = 0; i < 3; i++) {
            int k = tid + 256 * i;
            if (k < ntok) { float p = v[i] * inv; e += p * logf(p + 1e-6f); }
        }
        red[tid] = e; __syncthreads();
        for (int st = 128; st > 0; st >>= 1) { if (tid < st) red[tid] += red[tid + st]; __syncthreads(); }
        if (tid == 0) g_rho_bh[bh] = -red[0] / logf((float)ntok);
    }
}

// ---------------- out = attn @ V (64-row tiles, full d=64) ----------------
__global__ void __launch_bounds__(256) k_av(const float* __restrict__ qkv) {
    int ntok = g_Ntok;
    int q0 = blockIdx.x * 64; if (q0 >= ntok) return;
    int h = blockIdx.y, b = blockIdx.z;
    __shared__ float Ps[64][65];
    __shared__ float Vs[64][65];
    int tid = threadIdx.x, tx = tid & 15, ty = tid >> 4;
    float acc[4][4] = {};
    const float* Sb = g_S + ((size_t)(b * Hh + h)) * TMAX * SP;
    for (int k0 = 0; k0 < ntok; k0 += 64) {
        #pragma unroll
        for (int i = 0; i < 4; i++) {
            int idx = tid + i * 256;
            int r = idx >> 4, c4 = (idx & 15) * 4;
            int q = q0 + r;
            float4 pv = (q < ntok) ? *(const float4*)&Sb[(size_t)q * SP + k0 + c4]
                                   : make_float4(0.f, 0.f, 0.f, 0.f);
            Ps[r][c4] = pv.x; Ps[r][c4 + 1] = pv.y; Ps[r][c4 + 2] = pv.z; Ps[r][c4 + 3] = pv.w;
            int k = k0 + r;
            float4 vv = (k < ntok) ? *(const float4*)&qkv[((size_t)(b * TMAX + k)) * 1152 + 768 + h * 64 + c4]
                                   : make_float4(0.f, 0.f, 0.f, 0.f);
            Vs[r][c4] = vv.x; Vs[r][c4 + 1] = vv.y; Vs[r][c4 + 2] = vv.z; Vs[r][c4 + 3] = vv.w;
        }
        __syncthreads();
        #pragma unroll 8
        for (int kk = 0; kk < 64; kk++) {
            float a0 = Ps[ty * 4 + 0][kk], a1 = Ps[ty * 4 + 1][kk];
            float a2 = Ps[ty * 4 + 2][kk], a3 = Ps[ty * 4 + 3][kk];
            float b0 = Vs[kk][tx * 4 + 0], b1 = Vs[kk][tx * 4 + 1];
            float b2 = Vs[kk][tx * 4 + 2], b3 = Vs[kk][tx * 4 + 3];
            acc[0][0] += a0 * b0; acc[0][1] += a0 * b1; acc[0][2] += a0 * b2; acc[0][3] += a0 * b3;
            acc[1][0] += a1 * b0; acc[1][1] += a1 * b1; acc[1][2] += a1 * b2; acc[1][3] += a1 * b3;
            acc[2][0] += a2 * b0; acc[2][1] += a2 * b1; acc[2][2] += a2 * b2; acc[2][3] += a2 * b3;
            acc[3][0] += a3 * b0; acc[3][1] += a3 * b1; acc[3][2] += a3 * b2; acc[3][3] += a3 * b3;
        }
        __syncthreads();
    }
    #pragma unroll
    for (int i = 0; i < 4; i++) {
        int q = q0 + ty * 4 + i;
        if (q >= ntok) continue;
        #pragma unroll
        for (int j = 0; j < 4; j++)
            g_ao[((size_t)(b * TMAX + q)) * Dm + h * 64 + tx * 4 + j] = acc[i][j];
    }
}

// ---------------- stats: raw[b,k] = sum_h attn[b,h,0,k+1] * ||v[b,h,k+1]|| ----------------
__global__ void k_stats(const float* __restrict__ qkv) {
    int ntok = g_Ntok;
    int k = blockIdx.x * 192 + threadIdx.x;
    int b = blockIdx.y;
    if (k >= ntok - 1) return;
    const float4* vb = (const float4*)&qkv[((size_t)(b * TMAX + k + 1)) * 1152 + 768];
    const float* S0 = g_S + ((size_t)(b * Hh)) * TMAX * SP + (k + 1);
    float racc = 0.f;
    #pragma unroll
    for (int h = 0; h < Hh; h++) {
        float ss = 0.f;
        #pragma unroll
        for (int i = 0; i < 16; i++) {
            float4 v = vb[h * 16 + i];
            ss += v.x * v.x + v.y * v.y + v.z * v.z + v.w * v.w;
        }
        racc += S0[(size_t)h * TMAX * SP] * sqrtf(ss);
    }
    g_raw[b * NPATCH + k] = racc;
}

// ---------------- prune: mass + scores + controller + top-k + keep list ----------------
__global__ void k_prune() {
    __shared__ float sMass[Bc];
    __shared__ float wsum[Bc][18];
    __shared__ float sc[NPATCH];
    __shared__ unsigned char kp[NPATCH];
    __shared__ int sNn;
    int ntok = g_Ntok, Np = ntok - 1;
    int tid = threadIdx.x;
    int wid = tid >> 5, lid = tid & 31;

    // mass[b] = sum_k raw[b,k]
    #pragma unroll
    for (int b = 0; b < Bc; b++) {
        float v = (tid < Np) ? g_raw[b * NPATCH + tid] : 0.f;
        #pragma unroll
        for (int o = 16; o > 0; o >>= 1) v += __shfl_down_sync(0xffffffffu, v, o);
        if (lid == 0) wsum[b][wid] = v;
    }
    __syncthreads();
    if (tid < Bc) {
        float m = 0.f;
        for (int w = 0; w < 18; w++) m += wsum[tid][w];
        sMass[tid] = m;
    }
    __syncthreads();

    // scores
    float score = 0.f;
    if (tid < Np) {
        #pragma unroll
        for (int b = 0; b < Bc; b++) score += g_raw[b * NPATCH + tid] / (sMass[b] + 1e-6f);
        score *= 0.125f;
    }
    sc[tid] = score;

    // controller (thread 0)
    if (tid == 0) {
        int nn;
        if (Np > 16) {
            float mr = 0.f;
            for (int i = 0; i < Bc * Hh; i++) mr += g_rho_bh[i];
            mr /= 48.f;
            if (g_hasprev) {
                float md = 0.f;
                for (int b = 0; b < Bc; b++)
                    md += fabsf(sMass[b] - g_prevmass[b]) / (g_prevmass[b] + 1e-6f);
                md /= 8.f;
                float kr = 1.0f - 0.1f * (mr + md);
                kr = fminf(fmaxf(kr, 0.f), 1.f);
                nn = (int)((double)Np * (double)kr);
                if (nn < 16) nn = 16;
            } else {
                nn = Np;
            }
            for (int b = 0; b < Bc; b++) g_prevmass[b] = sMass[b];
            g_hasprev = 1;
        } else {
            nn = Np;
        }
        sNn = nn;
    }
    __syncthreads();
    int nn = sNn;

    // rank (exact lax.top_k tie-break: smaller index wins)
    int keep = 0;
    if (tid < Np) {
        float s = sc[tid];
        int rank = 0;
        for (int j = 0; j < Np; j++) {
            float o = sc[j];
            rank += (o > s) || (o == s && j < tid);
        }
        keep = (rank < nn);
    }
    kp[tid] = (unsigned char)keep;
    __syncthreads();
    if (keep) {
        int pos = 0;
        for (int j = 0; j < tid; j++) pos += kp[j];
        g_keep[pos + 1] = tid + 1;
    }
    if (tid == 0) { g_keep[0] = 0; g_Ntok = nn + 1; }
}

// ---------------- gather ----------------
__global__ void k_gather(const float* __restrict__ src, float* __restrict__ dst) {
    int ntok = g_Ntok;
    int t = blockIdx.x; if (t >= ntok) return;
    int b = blockIdx.y, d = threadIdx.x;
    int st = g_keep[t];
    ((float4*)&dst[((size_t)(b * TMAX + t)) * Dm])[d] =
        ((const float4*)&src[((size_t)(b * TMAX + st)) * Dm])[d];
}

// ---------------- classification head ----------------
__global__ void k_head(const float* __restrict__ xn, const float* __restrict__ W,
                       const float* __restrict__ bb, float* __restrict__ out) {
    int n = blockIdx.x * 128 + threadIdx.x;
    int b = blockIdx.y;
    if (n >= NCLSD) return;
    const float* xr = xn + (size_t)b * TMAX * Dm;
    float s = 0.f;
    for (int k = 0; k < Dm; k++) s += xr[k] * W[(size_t)k * NCLSD + n];
    out[b * NCLSD + n] = s + bb[n];
}

// ================================= host =================================
extern "C" void kernel_launch(void* const* d_in, const int* in_sizes, int n_in,
                              void* d_out, int out_size) {
    const float* x       = (const float*)d_in[0];
    const float* patch_w = (const float*)d_in[1];
    const float* patch_b = (const float*)d_in[2];
    const float* cls     = (const float*)d_in[3];
    const float* pos     = (const float*)d_in[4];
    const float* ln1_s   = (const float*)d_in[5];
    const float* ln1_b   = (const float*)d_in[6];
    const float* qkv_w   = (const float*)d_in[7];
    const float* qkv_b   = (const float*)d_in[8];
    const float* proj_w  = (const float*)d_in[9];
    const float* proj_b  = (const float*)d_in[10];
    const float* ln2_s   = (const float*)d_in[11];
    const float* ln2_b   = (const float*)d_in[12];
    const float* fc1_w   = (const float*)d_in[13];
    const float* fc1_b   = (const float*)d_in[14];
    const float* fc2_w   = (const float*)d_in[15];
    const float* fc2_b   = (const float*)d_in[16];
    const float* norm_s  = (const float*)d_in[17];
    const float* norm_b  = (const float*)d_in[18];
    const float* head_w  = (const float*)d_in[19];
    const float* head_b  = (const float*)d_in[20];
    float* out = (float*)d_out;

    float *pPatches, *pXA, *pXB, *pXn, *pQkv, *pAo, *pHid;
    cudaGetSymbolAddress((void**)&pPatches, g_patches);
    cudaGetSymbolAddress((void**)&pXA,  g_xA);
    cudaGetSymbolAddress((void**)&pXB,  g_xB);
    cudaGetSymbolAddress((void**)&pXn,  g_xn);
    cudaGetSymbolAddress((void**)&pQkv, g_qkv);
    cudaGetSymbolAddress((void**)&pAo,  g_ao);
    cudaGetSymbolAddress((void**)&pHid, g_hid);

    const int mT  = (MTOT + 63) / 64;            // 73 flattened M-tiles
    const int mTp = (Bc * NPATCH + 63) / 64;     // 72 for patch embed

    k_init<<<1, 1>>>();
    k_patchify<<<dim3(NPATCH, Bc), 256>>>(x);
    // tokens = patches @ patch_w + patch_b  -> g_ao used as [B][576][384] buffer
    k_gemm<<<dim3(Dm / 64, mTp), 256>>>(
        pPatches, Bc * NPATCH, 768, patch_w, Dm, patch_b, (const float*)0, pAo, 0, 0);
    k_embed<<<dim3(TMAX, Bc), 96>>>(cls, pos, pAo, pXA);

    float* src = pXA;
    float* dst = pXB;
    const int aTiles = (TMAX + 63) / 64;     // 10
    for (int l = 0; l < Lc; l++) {
        k_ln<<<dim3(TMAX, Bc), 128>>>(src, ln1_s + l * Dm, ln1_b + l * Dm, pXn, 1, 0);
        k_gemm<<<dim3(1152 / 64, mT), 256>>>(
            pXn, MTOT, Dm, qkv_w + (size_t)l * Dm * 1152, 1152, qkv_b + l * 1152,
            (const float*)0, pQkv, 0, 1);
        k_qk<<<dim3(aTiles, aTiles, Bc * Hh), 256>>>(pQkv);
        k_softmax<<<dim3(TMAX, Bc * Hh), 256>>>();
        k_av<<<dim3(aTiles, Hh, Bc), 256>>>(pQkv);
        k_stats<<<dim3(3, Bc), 192>>>(pQkv);
        k_gemm<<<dim3(Dm / 64, mT), 256>>>(
            pAo, MTOT, Dm, proj_w + (size_t)l * Dm * Dm, Dm, proj_b + l * Dm,
            src, src, 0, 1);
        k_ln<<<dim3(TMAX, Bc), 128>>>(src, ln2_s + l * Dm, ln2_b + l * Dm, pXn, 1, 0);
        k_gemm<<<dim3(MLPD / 64, mT), 256>>>(
            pXn, MTOT, Dm, fc1_w + (size_t)l * Dm * MLPD, MLPD, fc1_b + l * MLPD,
            (const float*)0, pHid, 1, 1);
        k_gemm<<<dim3(Dm / 64, mT), 256>>>(
            pHid, MTOT, MLPD, fc2_w + (size_t)l * MLPD * Dm, Dm, fc2_b + l * Dm,
            src, src, 0, 1);
        k_prune<<<1, NPATCH>>>();
        k_gather<<<dim3(TMAX, Bc), 96>>>(src, dst);
        float* tmp = src; src = dst; dst = tmp;
    }

    k_ln<<<dim3(1, Bc), 128>>>(src, norm_s, norm_b, pXn, 0, 1);
    k_head<<<dim3((NCLSD + 127) / 128, Bc), 128>>>(pXn, head_w, head_b, out);
}